// round 1
// baseline (speedup 1.0000x reference)
#include <cuda_runtime.h>
#include <math.h>

// Problem constants (fixed by the reference)
#define NND  50000          // nodes
#define FH   128            // F == H == 128
#define RR   8              // relations
#define EE   800000         // edges
#define NSEG (NND*RR)       // 400000 segments (dst*8 + type)
#define KC   1024           // R*H : K of the relation part of the big GEMM
#define BN_EPS 1e-5f

// ---------------- scratch (device globals: no allocs allowed) ----------------
__device__ float g_h[NND*FH];        // current node features
__device__ float g_c[NND*FH];        // conv output (pre-BN)
__device__ float g_agg[(size_t)NND*KC]; // per-(node,relation) aggregated messages [N,1024]
__device__ int   g_deg[NSEG];
__device__ int   g_rowptr[NSEG+1];
__device__ int   g_cursor[NSEG];
__device__ int   g_tmp[NSEG];
__device__ int   g_bsum[512];
__device__ int   g_esrc[EE];         // CSR payload: src node per edge, grouped by segment
__device__ float g_colsum[FH];
__device__ float g_colsq[FH];
__device__ float g_coef[2*FH];       // BN scale / shift
__device__ float g_w2o[FH+1];        // fused W2@Wo vector + fused bias

// ---------------- CSR build ----------------
__global__ void zero_deg_k() {
    int i = blockIdx.x*blockDim.x + threadIdx.x;
    if (i < NSEG) g_deg[i] = 0;
}

__global__ void hist_k(const int* __restrict__ dst, const int* __restrict__ et) {
    int e = blockIdx.x*blockDim.x + threadIdx.x;
    if (e < EE) atomicAdd(&g_deg[dst[e]*RR + et[e]], 1);
}

__global__ void scan1_k() {   // per-1024-chunk inclusive scan
    __shared__ int s[1024];
    int t = threadIdx.x;
    int i = blockIdx.x*1024 + t;
    int v = (i < NSEG) ? g_deg[i] : 0;
    s[t] = v; __syncthreads();
    for (int off = 1; off < 1024; off <<= 1) {
        int x = (t >= off) ? s[t-off] : 0;
        __syncthreads();
        s[t] += x;
        __syncthreads();
    }
    if (i < NSEG) g_tmp[i] = s[t];
    if (t == 1023) g_bsum[blockIdx.x] = s[t];
}

__global__ void scan2_k(int nb) {  // scan the 391 block sums (single block)
    __shared__ int s[512];
    int t = threadIdx.x;
    s[t] = (t < nb) ? g_bsum[t] : 0; __syncthreads();
    for (int off = 1; off < 512; off <<= 1) {
        int x = (t >= off) ? s[t-off] : 0;
        __syncthreads();
        s[t] += x;
        __syncthreads();
    }
    if (t < nb) g_bsum[t] = s[t];
}

__global__ void scan3_k() {
    int i = blockIdx.x*blockDim.x + threadIdx.x;
    if (i < NSEG) {
        int b = i >> 10;
        int incl = g_tmp[i] + (b > 0 ? g_bsum[b-1] : 0);
        g_rowptr[i+1] = incl;
        g_cursor[i]   = incl - g_deg[i];   // exclusive start
        if (i == 0) g_rowptr[0] = 0;
    }
}

__global__ void scatter_k(const int* __restrict__ src, const int* __restrict__ dst,
                          const int* __restrict__ et) {
    int e = blockIdx.x*blockDim.x + threadIdx.x;
    if (e < EE) {
        int s = dst[e]*RR + et[e];
        int pos = atomicAdd(&g_cursor[s], 1);
        g_esrc[pos] = src[e];
    }
}

// ---------------- segment gather-sum: agg[n][r*128+c] = sum_{edges} h[src][c] ----------------
__global__ void gather_k() {
    int w    = (blockIdx.x*blockDim.x + threadIdx.x) >> 5;   // one warp per segment
    int lane = threadIdx.x & 31;
    if (w >= NSEG) return;
    int beg = g_rowptr[w], end = g_rowptr[w+1];
    float4 acc = make_float4(0.f, 0.f, 0.f, 0.f);
    for (int e = beg; e < end; e++) {
        int s = g_esrc[e];
        float4 v = *((const float4*)(g_h + (size_t)s*FH) + lane);
        acc.x += v.x; acc.y += v.y; acc.z += v.z; acc.w += v.w;
    }
    int n = w >> 3, r = w & 7;
    *((float4*)(g_agg + (size_t)n*KC + r*FH) + lane) = acc;
}

// ---------------- fp32 SIMT GEMM: C[M,128] = A1[M,K1]*B1 + A2[M,K2]*B2 + bias ----------------
// BM=128, BN=128, BK=8, 256 threads, 8x8 per thread.
__global__ void __launch_bounds__(256, 2)
gemm_k(const float* __restrict__ A1, int K1,
       const float* __restrict__ A2, int K2,
       const float* __restrict__ B1, const float* __restrict__ B2,
       const float* __restrict__ bias,
       float* __restrict__ C, int M)
{
    __shared__ float As[8][128];
    __shared__ float Bs[8][128];
    int t  = threadIdx.x;
    int m0 = blockIdx.x * 128;
    int tr = t >> 4, tc = t & 15;
    int aRow = t >> 1, aC4 = t & 1;
    int bRow = t >> 5, bC4 = t & 31;

    float acc[8][8];
    #pragma unroll
    for (int i = 0; i < 8; i++)
        #pragma unroll
        for (int j = 0; j < 8; j++) acc[i][j] = 0.f;

    int Ktot = K1 + K2;
    for (int k0 = 0; k0 < Ktot; k0 += 8) {
        const float* A; const float* B; int lda; int kc;
        if (k0 < K1) { A = A1; B = B1; lda = K1; kc = k0; }
        else         { A = A2; B = B2; lda = K2; kc = k0 - K1; }

        float4 av = make_float4(0.f, 0.f, 0.f, 0.f);
        int gr = m0 + aRow;
        if (gr < M) av = *(const float4*)(A + (size_t)gr*lda + kc + aC4*4);
        As[aC4*4+0][aRow] = av.x;
        As[aC4*4+1][aRow] = av.y;
        As[aC4*4+2][aRow] = av.z;
        As[aC4*4+3][aRow] = av.w;

        float4 bv = *(const float4*)(B + (size_t)(kc + bRow)*128 + bC4*4);
        *(float4*)(&Bs[bRow][bC4*4]) = bv;
        __syncthreads();

        #pragma unroll
        for (int k = 0; k < 8; k++) {
            float ra[8], rb[8];
            #pragma unroll
            for (int i = 0; i < 8; i++) ra[i] = As[k][tr*8 + i];
            #pragma unroll
            for (int j = 0; j < 8; j++) rb[j] = Bs[k][tc*8 + j];
            #pragma unroll
            for (int i = 0; i < 8; i++)
                #pragma unroll
                for (int j = 0; j < 8; j++)
                    acc[i][j] += ra[i] * rb[j];
        }
        __syncthreads();
    }

    #pragma unroll
    for (int i = 0; i < 8; i++) {
        int gr = m0 + tr*8 + i;
        if (gr < M) {
            #pragma unroll
            for (int j = 0; j < 8; j += 4) {
                float4 o;
                o.x = acc[i][j+0] + bias[tc*8 + j + 0];
                o.y = acc[i][j+1] + bias[tc*8 + j + 1];
                o.z = acc[i][j+2] + bias[tc*8 + j + 2];
                o.w = acc[i][j+3] + bias[tc*8 + j + 3];
                *(float4*)(C + (size_t)gr*128 + tc*8 + j) = o;
            }
        }
    }
}

// ---------------- BatchNorm (training-mode: batch mean / biased var) ----------------
__global__ void zero_stats_k() {
    int c = threadIdx.x;
    if (c < FH) { g_colsum[c] = 0.f; g_colsq[c] = 0.f; }
}

__global__ void colstats_k(const float* __restrict__ C, int M) {
    int c = threadIdx.x;   // 128 threads: one column each
    float s = 0.f, q = 0.f;
    for (int r = blockIdx.x; r < M; r += gridDim.x) {
        float v = C[(size_t)r*FH + c];
        s += v; q += v * v;
    }
    atomicAdd(&g_colsum[c], s);
    atomicAdd(&g_colsq[c],  q);
}

__global__ void bncoef_k(const float* __restrict__ gamma, const float* __restrict__ beta) {
    int c = threadIdx.x;
    float mu  = g_colsum[c] / (float)NND;
    float var = g_colsq[c] / (float)NND - mu*mu;
    float sc  = gamma[c] * rsqrtf(var + BN_EPS);
    g_coef[c]      = sc;
    g_coef[FH + c] = beta[c] - mu * sc;
}

__global__ void bnrelu_k() {
    int i = blockIdx.x*blockDim.x + threadIdx.x;       // float4 index
    const int n4 = NND*FH/4;
    if (i < n4) {
        float4 v = *((const float4*)g_c + i);
        int cb = (i & 31) * 4;                          // column base (row = 32 float4s)
        v.x = fmaxf(v.x * g_coef[cb+0] + g_coef[FH+cb+0], 0.f);
        v.y = fmaxf(v.y * g_coef[cb+1] + g_coef[FH+cb+1], 0.f);
        v.z = fmaxf(v.z * g_coef[cb+2] + g_coef[FH+cb+2], 0.f);
        v.w = fmaxf(v.w * g_coef[cb+3] + g_coef[FH+cb+3], 0.f);
        *((float4*)g_h + i) = v;
    }
}

// ---------------- head: out = sigmoid(h @ (W2@Wo) + (b2@Wo + bo)) (exact fold) ----------------
__global__ void w2o_k(const float* __restrict__ W2, const float* __restrict__ b2,
                      const float* __restrict__ Wo, const float* __restrict__ bo) {
    int c = threadIdx.x;
    float s = 0.f;
    for (int j = 0; j < FH; j++) s += W2[c*FH + j] * Wo[j];
    g_w2o[c] = s;
    if (c == 0) {
        float b = bo[0];
        for (int j = 0; j < FH; j++) b += b2[j] * Wo[j];
        g_w2o[FH] = b;
    }
}

__global__ void head_k(float* __restrict__ out) {
    int w    = (blockIdx.x*blockDim.x + threadIdx.x) >> 5;   // one warp per node
    int lane = threadIdx.x & 31;
    if (w >= NND) return;
    float4 h  = *((const float4*)(g_h + (size_t)w*FH) + lane);
    float4 wv = *((const float4*)g_w2o + lane);
    float d = h.x*wv.x + h.y*wv.y + h.z*wv.z + h.w*wv.w;
    #pragma unroll
    for (int off = 16; off; off >>= 1) d += __shfl_down_sync(0xFFFFFFFFu, d, off);
    if (lane == 0) out[w] = 1.f / (1.f + expf(-(d + g_w2o[FH])));
}

// ---------------- launch ----------------
extern "C" void kernel_launch(void* const* d_in, const int* in_sizes, int n_in,
                              void* d_out, int out_size)
{
    const float* x      = (const float*)d_in[0];
    const int*   ei     = (const int*)  d_in[1];   // [2,E]: row0=src, row1=dst
    const int*   et     = (const int*)  d_in[2];
    const float* W1     = (const float*)d_in[3];
    const float* b1     = (const float*)d_in[4];
    const float* weight = (const float*)d_in[5];   // [R,H,H] -> flat [1024,128]
    const float* root   = (const float*)d_in[6];
    const float* bias_c = (const float*)d_in[7];
    const float* gamma  = (const float*)d_in[8];
    const float* beta   = (const float*)d_in[9];
    const float* W2     = (const float*)d_in[10];
    const float* b2     = (const float*)d_in[11];
    const float* Wo     = (const float*)d_in[12];
    const float* bo     = (const float*)d_in[13];
    float* out = (float*)d_out;

    float *hP, *cP, *aggP;
    cudaGetSymbolAddress((void**)&hP,   g_h);
    cudaGetSymbolAddress((void**)&cP,   g_c);
    cudaGetSymbolAddress((void**)&aggP, g_agg);

    const int T = 256;
    const int nScan1 = (NSEG + 1023) / 1024;   // 391

    // ---- CSR build (once; reused by both conv layers) ----
    zero_deg_k<<<(NSEG + T-1)/T, T>>>();
    hist_k<<<(EE + T-1)/T, T>>>(ei + EE, et);
    scan1_k<<<nScan1, 1024>>>();
    scan2_k<<<1, 512>>>(nScan1);
    scan3_k<<<(NSEG + T-1)/T, T>>>();
    scatter_k<<<(EE + T-1)/T, T>>>(ei, ei + EE, et);

    const int gemmGrid = (NND + 127) / 128;    // 391

    // ---- layer 1: h = x @ W1 + b1 ----
    gemm_k<<<gemmGrid, 256>>>(x, FH, x, 0, W1, W1, b1, hP, NND);

    // ---- two conv + BN + ReLU layers ----
    for (int layer = 0; layer < 2; layer++) {
        gather_k<<<(NSEG*32 + T-1)/T, T>>>();
        gemm_k<<<gemmGrid, 256>>>(aggP, KC, hP, FH, weight, root, bias_c, cP, NND);
        zero_stats_k<<<1, FH>>>();
        colstats_k<<<512, FH>>>(cP, NND);
        bncoef_k<<<1, FH>>>(gamma, beta);
        bnrelu_k<<<(NND*FH/4 + T-1)/T, T>>>();
    }

    // ---- folded head ----
    w2o_k<<<1, FH>>>(W2, b2, Wo, bo);
    head_k<<<(NND*32 + T-1)/T, T>>>(out);
}

// round 3
// speedup vs baseline: 2.3515x; 2.3515x over previous
#include <cuda_runtime.h>
#include <cuda_bf16.h>
#include <math.h>
#include <stdint.h>

// Problem constants (fixed by the reference)
#define NND  50000          // nodes
#define FH   128            // F == H == 128
#define RR   8              // relations
#define EE   800000         // edges
#define NSEG (NND*RR)       // 400000 segments (dst*8 + type)
#define KC   1024           // R*H
#define KCONV (KC+FH)       // 1152
#define BN_EPS 1e-5f

// ---------------- scratch (device globals: no allocs allowed) ----------------
__device__ __align__(16) float g_h[NND*FH];        // current node features (fp32)
__device__ __align__(16) float g_c[NND*FH];        // conv output (pre-BN)
// A operand for conv GEMM, bf16 split: cols 0..1023 = agg, 1024..1151 = h
__device__ __align__(16) __nv_bfloat16 g_aggh_hi[(size_t)NND*KCONV];
__device__ __align__(16) __nv_bfloat16 g_aggh_lo[(size_t)NND*KCONV];
__device__ int   g_deg[NSEG];
__device__ int   g_rowptr[NSEG+1];
__device__ int   g_cursor[NSEG];
__device__ int   g_tmp[NSEG];
__device__ int   g_bsum[512];
__device__ int   g_esrc[EE];
__device__ float g_colsum[FH];
__device__ float g_colsq[FH];
__device__ float g_coef[2*FH];
__device__ float g_w2o[FH+1];
// pre-split, pre-transposed B matrices (bf16 hi/lo, [N=128][K] K-major)
__device__ __align__(16) __nv_bfloat16 g_Bc_hi[FH*KCONV];
__device__ __align__(16) __nv_bfloat16 g_Bc_lo[FH*KCONV];
__device__ __align__(16) __nv_bfloat16 g_B1_hi[FH*FH];
__device__ __align__(16) __nv_bfloat16 g_B1_lo[FH*FH];

// ---------------- CSR build ----------------
__global__ void zero_deg_k() {
    int i = blockIdx.x*blockDim.x + threadIdx.x;
    if (i < NSEG) g_deg[i] = 0;
}
__global__ void hist_k(const int* __restrict__ dst, const int* __restrict__ et) {
    int e = blockIdx.x*blockDim.x + threadIdx.x;
    if (e < EE) atomicAdd(&g_deg[dst[e]*RR + et[e]], 1);
}
__global__ void scan1_k() {
    __shared__ int s[1024];
    int t = threadIdx.x;
    int i = blockIdx.x*1024 + t;
    int v = (i < NSEG) ? g_deg[i] : 0;
    s[t] = v; __syncthreads();
    for (int off = 1; off < 1024; off <<= 1) {
        int x = (t >= off) ? s[t-off] : 0;
        __syncthreads(); s[t] += x; __syncthreads();
    }
    if (i < NSEG) g_tmp[i] = s[t];
    if (t == 1023) g_bsum[blockIdx.x] = s[t];
}
__global__ void scan2_k(int nb) {
    __shared__ int s[512];
    int t = threadIdx.x;
    s[t] = (t < nb) ? g_bsum[t] : 0; __syncthreads();
    for (int off = 1; off < 512; off <<= 1) {
        int x = (t >= off) ? s[t-off] : 0;
        __syncthreads(); s[t] += x; __syncthreads();
    }
    if (t < nb) g_bsum[t] = s[t];
}
__global__ void scan3_k() {
    int i = blockIdx.x*blockDim.x + threadIdx.x;
    if (i < NSEG) {
        int b = i >> 10;
        int incl = g_tmp[i] + (b > 0 ? g_bsum[b-1] : 0);
        g_rowptr[i+1] = incl;
        g_cursor[i]   = incl - g_deg[i];
        if (i == 0) g_rowptr[0] = 0;
    }
}
__global__ void scatter_k(const int* __restrict__ src, const int* __restrict__ dst,
                          const int* __restrict__ et) {
    int e = blockIdx.x*blockDim.x + threadIdx.x;
    if (e < EE) {
        int s = dst[e]*RR + et[e];
        int pos = atomicAdd(&g_cursor[s], 1);
        g_esrc[pos] = src[e];
    }
}

// ---------------- prep: transpose + bf16-split B matrices ----------------
__global__ void prepB_k(const float* __restrict__ W1, const float* __restrict__ weight,
                        const float* __restrict__ root) {
    int i = blockIdx.x*blockDim.x + threadIdx.x;
    const int totC = FH*KCONV;
    if (i < totC) {
        int n = i / KCONV, k = i % KCONV;
        float v = (k < KC) ? weight[(size_t)k*FH + n] : root[(size_t)(k-KC)*FH + n];
        __nv_bfloat16 h = __float2bfloat16_rn(v);
        g_Bc_hi[i] = h;
        g_Bc_lo[i] = __float2bfloat16_rn(v - __bfloat162float(h));
    } else if (i < totC + FH*FH) {
        int j = i - totC;
        int n = j / FH, k = j % FH;
        float v = W1[(size_t)k*FH + n];
        __nv_bfloat16 h = __float2bfloat16_rn(v);
        g_B1_hi[j] = h;
        g_B1_lo[j] = __float2bfloat16_rn(v - __bfloat162float(h));
    }
}

// ---------------- prep x: split into bf16 hi/lo at aggh cols 1024.. ----------------
__global__ void prepX_k(const float* __restrict__ x) {
    int i = blockIdx.x*blockDim.x + threadIdx.x;   // over NND*FH
    if (i < NND*FH) {
        int m = i >> 7, c = i & 127;
        float v = x[i];
        __nv_bfloat16 h = __float2bfloat16_rn(v);
        size_t off = (size_t)m*KCONV + KC + c;
        g_aggh_hi[off] = h;
        g_aggh_lo[off] = __float2bfloat16_rn(v - __bfloat162float(h));
    }
}

// ---------------- segment gather-sum -> bf16 hi/lo agg ----------------
__global__ void gather_k() {
    int w    = (blockIdx.x*blockDim.x + threadIdx.x) >> 5;   // one warp per segment
    int lane = threadIdx.x & 31;
    if (w >= NSEG) return;
    int beg = g_rowptr[w], end = g_rowptr[w+1];
    float4 acc = make_float4(0.f, 0.f, 0.f, 0.f);
    for (int e = beg; e < end; e++) {
        int s = g_esrc[e];
        float4 v = *((const float4*)(g_h + (size_t)s*FH) + lane);
        acc.x += v.x; acc.y += v.y; acc.z += v.z; acc.w += v.w;
    }
    int n = w >> 3, r = w & 7;
    __nv_bfloat162 h0, h1, l0, l1;
    h0.x = __float2bfloat16_rn(acc.x); h0.y = __float2bfloat16_rn(acc.y);
    h1.x = __float2bfloat16_rn(acc.z); h1.y = __float2bfloat16_rn(acc.w);
    l0.x = __float2bfloat16_rn(acc.x - __bfloat162float(h0.x));
    l0.y = __float2bfloat16_rn(acc.y - __bfloat162float(h0.y));
    l1.x = __float2bfloat16_rn(acc.z - __bfloat162float(h1.x));
    l1.y = __float2bfloat16_rn(acc.w - __bfloat162float(h1.y));
    size_t off = (size_t)n*KCONV + r*FH + lane*4;
    uint2 hv, lv;
    hv.x = *reinterpret_cast<uint32_t*>(&h0); hv.y = *reinterpret_cast<uint32_t*>(&h1);
    lv.x = *reinterpret_cast<uint32_t*>(&l0); lv.y = *reinterpret_cast<uint32_t*>(&l1);
    *reinterpret_cast<uint2*>(g_aggh_hi + off) = hv;
    *reinterpret_cast<uint2*>(g_aggh_lo + off) = lv;
}

// ---------------- mma.sync split-bf16 GEMM ----------------
// C[M,128] = A[M,Kt]*B[Kt,128] + bias (A = Ahi+Alo, B = Bhi+Blo pre-split bf16)
// Block 128x128, BK=32, 2-stage cp.async, 8 warps -> 64x32 warp tiles.
#define ASTRIDE 80                       // bytes per smem row (32 bf16 + 8 pad)
#define ARRB    (128*ASTRIDE)            // 10240 bytes per array
#define STGB    (4*ARRB)                 // Ah, Al, Bh, Bl
#define SMEM_GEMM (2*STGB)               // 81920

__device__ __forceinline__ uint32_t smem_u32(const void* p) {
    uint32_t a;
    asm("{ .reg .u64 t; cvta.to.shared.u64 t, %1; cvt.u32.u64 %0, t; }" : "=r"(a) : "l"(p));
    return a;
}
__device__ __forceinline__ void mma_bf16(float* c, const uint32_t* a, const uint32_t* b) {
    asm volatile("mma.sync.aligned.m16n8k16.row.col.f32.bf16.bf16.f32 "
        "{%0,%1,%2,%3}, {%4,%5,%6,%7}, {%8,%9}, {%0,%1,%2,%3};"
        : "+f"(c[0]), "+f"(c[1]), "+f"(c[2]), "+f"(c[3])
        : "r"(a[0]), "r"(a[1]), "r"(a[2]), "r"(a[3]), "r"(b[0]), "r"(b[1]));
}

__global__ void __launch_bounds__(256)
mmagemm_k(const __nv_bfloat16* __restrict__ Ah, const __nv_bfloat16* __restrict__ Al, int lda,
          int Kt,
          const __nv_bfloat16* __restrict__ Bh, const __nv_bfloat16* __restrict__ Bl, int ldb,
          const float* __restrict__ bias,
          float* __restrict__ Cf,                   // mode1: plain fp32 out
          float* __restrict__ Hf,                   // mode0: fp32 h out (+hi/lo below)
          __nv_bfloat16* __restrict__ Hhi, __nv_bfloat16* __restrict__ Hlo, int hstride,
          int M)
{
    extern __shared__ char sm[];
    uint32_t smb = smem_u32(sm);
    int t = threadIdx.x, lane = t & 31, wid = t >> 5;
    int m0 = blockIdx.x * 128;
    int wm = (wid >> 2) * 64, wn = (wid & 3) * 32;
    int g = lane >> 2, tig = lane & 3;
    int nsteps = Kt >> 5;

    auto load_stage = [&](int s, int slot) {
        int kc = s << 5;
        #pragma unroll
        for (int i = 0; i < 8; i++) {
            int c = t + i*256;
            int arr = c >> 9, row = (c >> 2) & 127, col = c & 3;
            uint32_t dst = smb + slot*STGB + arr*ARRB + row*ASTRIDE + col*16;
            const __nv_bfloat16* src;
            int sz = 16;
            if (arr < 2) {
                int m = m0 + row;
                if (m >= M) { m = 0; sz = 0; }
                src = (arr ? Al : Ah) + (size_t)m*lda + kc + col*8;
            } else {
                src = (arr == 3 ? Bl : Bh) + (size_t)row*ldb + kc + col*8;
            }
            asm volatile("cp.async.cg.shared.global [%0], [%1], 16, %2;"
                         :: "r"(dst), "l"(src), "r"(sz) : "memory");
        }
        asm volatile("cp.async.commit_group;" ::: "memory");
    };

    float acc[4][4][4];
    #pragma unroll
    for (int a = 0; a < 4; a++)
        #pragma unroll
        for (int b = 0; b < 4; b++)
            #pragma unroll
            for (int q = 0; q < 4; q++) acc[a][b][q] = 0.f;

    load_stage(0, 0);
    load_stage(1, 1);

    for (int s = 0; s < nsteps; s++) {
        asm volatile("cp.async.wait_group 1;" ::: "memory");
        __syncthreads();
        const char* bs = sm + (s & 1)*STGB;
        #pragma unroll
        for (int kk = 0; kk < 2; kk++) {
            int kbyte = kk*32 + tig*4;   // byte offset of (k16*16 + tig*2) bf16
            uint32_t ah[4][4], al[4][4], bh[4][2], bl[4][2];
            #pragma unroll
            for (int mi = 0; mi < 4; mi++) {
                const char* p = bs + (wm + mi*16 + g)*ASTRIDE + kbyte;
                ah[mi][0] = *(const uint32_t*)(p);
                ah[mi][1] = *(const uint32_t*)(p + 8*ASTRIDE);
                ah[mi][2] = *(const uint32_t*)(p + 16);
                ah[mi][3] = *(const uint32_t*)(p + 8*ASTRIDE + 16);
                const char* q = p + ARRB;
                al[mi][0] = *(const uint32_t*)(q);
                al[mi][1] = *(const uint32_t*)(q + 8*ASTRIDE);
                al[mi][2] = *(const uint32_t*)(q + 16);
                al[mi][3] = *(const uint32_t*)(q + 8*ASTRIDE + 16);
            }
            #pragma unroll
            for (int ni = 0; ni < 4; ni++) {
                const char* p = bs + 2*ARRB + (wn + ni*8 + g)*ASTRIDE + kbyte;
                bh[ni][0] = *(const uint32_t*)(p);
                bh[ni][1] = *(const uint32_t*)(p + 16);
                const char* q = p + ARRB;
                bl[ni][0] = *(const uint32_t*)(q);
                bl[ni][1] = *(const uint32_t*)(q + 16);
            }
            #pragma unroll
            for (int mi = 0; mi < 4; mi++)
                #pragma unroll
                for (int ni = 0; ni < 4; ni++) {
                    mma_bf16(acc[mi][ni], ah[mi], bh[ni]);
                    mma_bf16(acc[mi][ni], al[mi], bh[ni]);
                    mma_bf16(acc[mi][ni], ah[mi], bl[ni]);
                }
        }
        __syncthreads();
        if (s + 2 < nsteps) load_stage(s + 2, s & 1);
        else asm volatile("cp.async.commit_group;" ::: "memory");
    }
    asm volatile("cp.async.wait_group 0;" ::: "memory");

    // epilogue
    #pragma unroll
    for (int mi = 0; mi < 4; mi++)
        #pragma unroll
        for (int ni = 0; ni < 4; ni++) {
            int n = wn + ni*8 + tig*2;
            float b0 = bias[n], b1 = bias[n+1];
            #pragma unroll
            for (int h2 = 0; h2 < 2; h2++) {
                int m = m0 + wm + mi*16 + g + h2*8;
                if (m < M) {
                    float v0 = acc[mi][ni][2*h2]   + b0;
                    float v1 = acc[mi][ni][2*h2+1] + b1;
                    if (Hf) {
                        float2 f2; f2.x = v0; f2.y = v1;
                        *(float2*)(Hf + (size_t)m*FH + n) = f2;
                        __nv_bfloat162 hh, ll;
                        hh.x = __float2bfloat16_rn(v0);
                        hh.y = __float2bfloat16_rn(v1);
                        ll.x = __float2bfloat16_rn(v0 - __bfloat162float(hh.x));
                        ll.y = __float2bfloat16_rn(v1 - __bfloat162float(hh.y));
                        *(__nv_bfloat162*)(Hhi + (size_t)m*hstride + n) = hh;
                        *(__nv_bfloat162*)(Hlo + (size_t)m*hstride + n) = ll;
                    } else {
                        float2 f2; f2.x = v0; f2.y = v1;
                        *(float2*)(Cf + (size_t)m*FH + n) = f2;
                    }
                }
            }
        }
}

// ---------------- BatchNorm ----------------
__global__ void zero_stats_k() {
    int c = threadIdx.x;
    if (c < FH) { g_colsum[c] = 0.f; g_colsq[c] = 0.f; }
}
__global__ void colstats_k(const float* __restrict__ C, int M) {
    int c = threadIdx.x;
    float s = 0.f, q = 0.f;
    for (int r = blockIdx.x; r < M; r += gridDim.x) {
        float v = C[(size_t)r*FH + c];
        s += v; q += v * v;
    }
    atomicAdd(&g_colsum[c], s);
    atomicAdd(&g_colsq[c],  q);
}
__global__ void bncoef_k(const float* __restrict__ gamma, const float* __restrict__ beta) {
    int c = threadIdx.x;
    float mu  = g_colsum[c] / (float)NND;
    float var = g_colsq[c] / (float)NND - mu*mu;
    float sc  = gamma[c] * rsqrtf(var + BN_EPS);
    g_coef[c]      = sc;
    g_coef[FH + c] = beta[c] - mu * sc;
}
// BN+ReLU: write fp32 h AND bf16 hi/lo h into aggh cols 1024..
__global__ void bnrelu_k() {
    int i = blockIdx.x*blockDim.x + threadIdx.x;
    const int n4 = NND*FH/4;
    if (i < n4) {
        float4 v = *((const float4*)g_c + i);
        int cb = (i & 31) * 4;
        int row = i >> 5;
        v.x = fmaxf(v.x * g_coef[cb+0] + g_coef[FH+cb+0], 0.f);
        v.y = fmaxf(v.y * g_coef[cb+1] + g_coef[FH+cb+1], 0.f);
        v.z = fmaxf(v.z * g_coef[cb+2] + g_coef[FH+cb+2], 0.f);
        v.w = fmaxf(v.w * g_coef[cb+3] + g_coef[FH+cb+3], 0.f);
        *((float4*)g_h + i) = v;
        __nv_bfloat162 h0, h1, l0, l1;
        h0.x = __float2bfloat16_rn(v.x); h0.y = __float2bfloat16_rn(v.y);
        h1.x = __float2bfloat16_rn(v.z); h1.y = __float2bfloat16_rn(v.w);
        l0.x = __float2bfloat16_rn(v.x - __bfloat162float(h0.x));
        l0.y = __float2bfloat16_rn(v.y - __bfloat162float(h0.y));
        l1.x = __float2bfloat16_rn(v.z - __bfloat162float(h1.x));
        l1.y = __float2bfloat16_rn(v.w - __bfloat162float(h1.y));
        size_t off = (size_t)row*KCONV + KC + cb;
        uint2 hv, lv;
        hv.x = *reinterpret_cast<uint32_t*>(&h0); hv.y = *reinterpret_cast<uint32_t*>(&h1);
        lv.x = *reinterpret_cast<uint32_t*>(&l0); lv.y = *reinterpret_cast<uint32_t*>(&l1);
        *reinterpret_cast<uint2*>(g_aggh_hi + off) = hv;
        *reinterpret_cast<uint2*>(g_aggh_lo + off) = lv;
    }
}

// ---------------- head ----------------
__global__ void w2o_k(const float* __restrict__ W2, const float* __restrict__ b2,
                      const float* __restrict__ Wo, const float* __restrict__ bo) {
    int c = threadIdx.x;
    float s = 0.f;
    for (int j = 0; j < FH; j++) s += W2[c*FH + j] * Wo[j];
    g_w2o[c] = s;
    if (c == 0) {
        float b = bo[0];
        for (int j = 0; j < FH; j++) b += b2[j] * Wo[j];
        g_w2o[FH] = b;
    }
}
__global__ void head_k(float* __restrict__ out) {
    int w    = (blockIdx.x*blockDim.x + threadIdx.x) >> 5;
    int lane = threadIdx.x & 31;
    if (w >= NND) return;
    float4 h  = *((const float4*)(g_h + (size_t)w*FH) + lane);
    float4 wv = *((const float4*)g_w2o + lane);
    float d = h.x*wv.x + h.y*wv.y + h.z*wv.z + h.w*wv.w;
    #pragma unroll
    for (int off = 16; off; off >>= 1) d += __shfl_down_sync(0xFFFFFFFFu, d, off);
    if (lane == 0) out[w] = 1.f / (1.f + expf(-(d + g_w2o[FH])));
}

// ---------------- launch ----------------
extern "C" void kernel_launch(void* const* d_in, const int* in_sizes, int n_in,
                              void* d_out, int out_size)
{
    const float* x      = (const float*)d_in[0];
    const int*   ei     = (const int*)  d_in[1];
    const int*   et     = (const int*)  d_in[2];
    const float* W1     = (const float*)d_in[3];
    const float* b1     = (const float*)d_in[4];
    const float* weight = (const float*)d_in[5];
    const float* root   = (const float*)d_in[6];
    const float* bias_c = (const float*)d_in[7];
    const float* gamma  = (const float*)d_in[8];
    const float* beta   = (const float*)d_in[9];
    const float* W2     = (const float*)d_in[10];
    const float* b2     = (const float*)d_in[11];
    const float* Wo     = (const float*)d_in[12];
    const float* bo     = (const float*)d_in[13];
    float* out = (float*)d_out;

    float *hP, *cP;
    __nv_bfloat16 *AHi, *ALo, *BcHi, *BcLo, *B1Hi, *B1Lo;
    cudaGetSymbolAddress((void**)&hP,   g_h);
    cudaGetSymbolAddress((void**)&cP,   g_c);
    cudaGetSymbolAddress((void**)&AHi,  g_aggh_hi);
    cudaGetSymbolAddress((void**)&ALo,  g_aggh_lo);
    cudaGetSymbolAddress((void**)&BcHi, g_Bc_hi);
    cudaGetSymbolAddress((void**)&BcLo, g_Bc_lo);
    cudaGetSymbolAddress((void**)&B1Hi, g_B1_hi);
    cudaGetSymbolAddress((void**)&B1Lo, g_B1_lo);

    cudaFuncSetAttribute(mmagemm_k, cudaFuncAttributeMaxDynamicSharedMemorySize, SMEM_GEMM);

    const int T = 256;
    const int nScan1 = (NSEG + 1023) / 1024;

    // ---- CSR build ----
    zero_deg_k<<<(NSEG + T-1)/T, T>>>();
    hist_k<<<(EE + T-1)/T, T>>>(ei + EE, et);
    scan1_k<<<nScan1, 1024>>>();
    scan2_k<<<1, 512>>>(nScan1);
    scan3_k<<<(NSEG + T-1)/T, T>>>();
    scatter_k<<<(EE + T-1)/T, T>>>(ei, ei + EE, et);

    // ---- prep: B matrices + x split ----
    prepB_k<<<(FH*KCONV + FH*FH + T-1)/T, T>>>(W1, weight, root);
    prepX_k<<<(NND*FH + T-1)/T, T>>>(x);

    const int gemmGrid = (NND + 127) / 128;   // 391

    // ---- layer 1: h = x @ W1 + b1 (A = aggh cols 1024.., K=128) ----
    mmagemm_k<<<gemmGrid, 256, SMEM_GEMM>>>(
        AHi + KC, ALo + KC, KCONV, FH,
        B1Hi, B1Lo, FH, b1,
        nullptr, hP, AHi + KC, ALo + KC, KCONV, NND);

    // ---- two conv + BN + ReLU layers ----
    for (int layer = 0; layer < 2; layer++) {
        gather_k<<<(NSEG*32 + T-1)/T, T>>>();
        mmagemm_k<<<gemmGrid, 256, SMEM_GEMM>>>(
            AHi, ALo, KCONV, KCONV,
            BcHi, BcLo, KCONV, bias_c,
            cP, nullptr, nullptr, nullptr, 0, NND);
        zero_stats_k<<<1, FH>>>();
        colstats_k<<<512, FH>>>(cP, NND);
        bncoef_k<<<1, FH>>>(gamma, beta);
        bnrelu_k<<<(NND*FH/4 + T-1)/T, T>>>();
    }

    // ---- folded head ----
    w2o_k<<<1, FH>>>(W2, b2, Wo, bo);
    head_k<<<(NND*32 + T-1)/T, T>>>(out);
}